// round 4
// baseline (speedup 1.0000x reference)
#include <cuda_runtime.h>
#include <math.h>

#define NN    50000      // nodes
#define NE    800000     // edges
#define NG    512        // graphs
#define HID   128
#define RBF   32
#define NL    6
#define TBL   5120       // LUT grid points per layer
#define DMAX  5.0f       // beyond this, rbf == 0 to fp32 precision

typedef unsigned long long u64;

// ---------------- device scratch (static allocations only) ----------------
__device__ float g_h    [NN * HID];        // node features
__device__ float g_aggr [NN * HID];        // aggregated messages / e2 reuse
__device__ float g_table[NL * TBL * HID];  // W_l(d) lookup table
__device__ int   g_deg  [NN];
__device__ float g_invd [NN];
__device__ int   g_off  [NN + 1];
__device__ int   g_cur  [NN];              // near fill pointer
__device__ int   g_curf [NN];              // far fill pointer (top, exclusive)
__device__ int   g_mid  [NN];              // near/far boundary
__device__ int2  g_jt   [NE];              // CSR: {neighbor j, tt bits}
__device__ int   g_se   [NE];              // CSR: original edge id (sort key)

__device__ __forceinline__ float sspf(float x) {
    return fmaxf(x, 0.0f) + log1pf(expf(-fabsf(x))) - 0.5f;
}

__device__ __forceinline__ u64 pack2(float lo, float hi) {
    u64 r;
    asm("mov.b64 %0, {%1, %2};" : "=l"(r) : "f"(lo), "f"(hi));
    return r;
}
__device__ __forceinline__ void unpack2(u64 v, float& lo, float& hi) {
    asm("mov.b64 {%0, %1}, %2;" : "=f"(lo), "=f"(hi) : "l"(v));
}
__device__ __forceinline__ void ffma2(u64& d, u64 a, u64 b) {
    asm("fma.rn.f32x2 %0, %1, %2, %0;" : "+l"(d) : "l"(a), "l"(b));
}

// ---------------- init: h = embed[z], zero deg ----------------
__global__ void k_init(const int* __restrict__ z, const float* __restrict__ embed) {
    int tid  = blockIdx.x * blockDim.x + threadIdx.x;   // NN*32 threads exactly
    int n    = tid >> 5;
    int lane = tid & 31;
    if (lane == 0) g_deg[n] = 0;
    int zz = z[n];
    float4 v = *(const float4*)(embed + (size_t)zz * HID + lane * 4);
    *(float4*)(g_h + (size_t)n * HID + lane * 4) = v;
}

// ---------------- degree count ----------------
__global__ void k_deg(const int* __restrict__ ei) {
    int e = blockIdx.x * blockDim.x + threadIdx.x;      // NE threads exactly
    atomicAdd(&g_deg[ei[e]], 1);
}

// ---------------- single-block exclusive scan over degrees ----------------
__global__ void k_scan() {
    __shared__ int sums[1024];
    const int t = threadIdx.x;
    const int CH = 49;                                  // 1024*49 >= NN
    int base = t * CH;
    int s = 0;
    for (int u = 0; u < CH; u++) {
        int idx = base + u;
        if (idx < NN) s += g_deg[idx];
    }
    sums[t] = s;
    __syncthreads();
    for (int o = 1; o < 1024; o <<= 1) {
        int v = (t >= o) ? sums[t - o] : 0;
        __syncthreads();
        sums[t] += v;
        __syncthreads();
    }
    int run = (t == 0) ? 0 : sums[t - 1];
    for (int u = 0; u < CH; u++) {
        int idx = base + u;
        if (idx < NN) {
            int d = g_deg[idx];
            g_off[idx]  = run;
            g_cur[idx]  = run;          // near fills upward from lo
            g_curf[idx] = run + d;      // far fills downward from hi
            g_invd[idx] = 1.0f / (float)max(d, 1);
            run += d;
        }
    }
    if (t == 1023) g_off[NN] = sums[1023];
}

// ------- compute d, scatter edges into partitioned CSR buckets -------------
__global__ void k_scatter(const int* __restrict__ ei, const float* __restrict__ pos) {
    int e = blockIdx.x * blockDim.x + threadIdx.x;      // NE threads exactly
    int i = ei[e];
    int j = ei[NE + e];
    float dx = pos[3 * i + 0] - pos[3 * j + 0];
    float dy = pos[3 * i + 1] - pos[3 * j + 1];
    float dz = pos[3 * i + 2] - pos[3 * j + 2];
    float d  = sqrtf(dx * dx + dy * dy + dz * dz);
    const float inv_step = (float)(TBL - 1) / DMAX;
    float tt = fminf(d * inv_step, (float)(TBL - 1));
    int p;
    if (tt >= (float)(TBL - 1)) {
        p = atomicAdd(&g_curf[i], -1) - 1;              // far segment (top-down)
    } else {
        p = atomicAdd(&g_cur[i], 1);                    // near segment (bottom-up)
    }
    g_jt[p] = make_int2(j, __float_as_int(tt));
    g_se[p] = e;
}

// --- deterministic order: insertion sort each near/far segment by edge id --
__global__ void k_sort() {
    int n = blockIdx.x * blockDim.x + threadIdx.x;
    if (n >= NN) return;
    int lo  = g_off[n], hi = g_off[n + 1];
    int mid = g_cur[n];                                 // == g_curf[n] now
    g_mid[n] = mid;
    #pragma unroll 2
    for (int seg = 0; seg < 2; seg++) {
        int s0 = seg ? mid : lo;
        int s1 = seg ? hi  : mid;
        for (int a = s0 + 1; a < s1; a++) {
            int  ke = g_se[a];
            int2 kv = g_jt[a];
            int b = a - 1;
            while (b >= s0 && g_se[b] > ke) {
                g_se[b + 1] = g_se[b];
                g_jt[b + 1] = g_jt[b];
                b--;
            }
            g_se[b + 1] = ke;
            g_jt[b + 1] = kv;
        }
    }
}

// ---------------- build W_l(d) table: 8 grid points per block --------------
__global__ void k_table(const float* __restrict__ fw1, const float* __restrict__ fb1,
                        const float* __restrict__ fw2, const float* __restrict__ fb2) {
    const int PG = 8;
    int gid = blockIdx.x * PG;          // over NL*TBL
    int l   = gid / TBL;
    int g0  = gid - l * TBL;
    int c   = threadIdx.x;              // 128 threads
    __shared__ float rbf [PG][RBF];
    __shared__ float sspt[PG][HID];
    const float step   = DMAX / (float)(TBL - 1);
    const float cspace = 4.0f / 31.0f;

    for (int u = c; u < PG * RBF; u += HID) {
        int p = u >> 5, k = u & 31;
        float d = (float)(g0 + p) * step;
        float x = d - (float)k * cspace;
        rbf[p][k] = expf(-32.0f * x * x);
    }
    __syncthreads();

    float acc[PG];
    float b1 = fb1[l * HID + c];
    #pragma unroll
    for (int p = 0; p < PG; p++) acc[p] = b1;
    for (int k = 0; k < RBF; k++) {
        float f = fw1[(size_t)(l * RBF + k) * HID + c];
        #pragma unroll
        for (int p = 0; p < PG; p++) acc[p] = fmaf(rbf[p][k], f, acc[p]);
    }
    #pragma unroll
    for (int p = 0; p < PG; p++) sspt[p][c] = sspf(acc[p]);
    __syncthreads();

    float b2 = fb2[l * HID + c];
    #pragma unroll
    for (int p = 0; p < PG; p++) acc[p] = b2;
    for (int m = 0; m < HID; m++) {
        float f = fw2[(size_t)(l * HID + m) * HID + c];
        #pragma unroll
        for (int p = 0; p < PG; p++) acc[p] = fmaf(sspt[p][m], f, acc[p]);
    }
    #pragma unroll
    for (int p = 0; p < PG; p++)
        g_table[((size_t)l * TBL + g0 + p) * HID + c] = acc[p];
}

// ------ per-layer edge aggregation: one warp per node, split loops ---------
__global__ void k_edge(int l) {
    int w    = (blockIdx.x * blockDim.x + threadIdx.x) >> 5;  // == node, exact
    int lane = threadIdx.x & 31;
    const int lo  = g_off[w];
    const int mid = g_mid[w];
    const int hi  = g_off[w + 1];
    const float* tab = g_table + (size_t)l * TBL * HID;

    // ---- near loop: lerp path, unroll 2 ----
    float nx = 0.f, ny = 0.f, nz = 0.f, nw = 0.f;
    int e = lo;
    for (; e + 2 <= mid; e += 2) {
        int2  jt0 = __ldg(&g_jt[e]);
        int2  jt1 = __ldg(&g_jt[e + 1]);
        float tt0 = __int_as_float(jt0.y);
        float tt1 = __int_as_float(jt1.y);
        int   i0  = (int)tt0;
        int   i1  = (int)tt1;
        float fr0 = tt0 - (float)i0;
        float fr1 = tt1 - (float)i1;
        float4 h0  = *(const float4*)(g_h + (size_t)jt0.x * HID + lane * 4);
        float4 wl0 = *(const float4*)(tab + (size_t)i0 * HID + lane * 4);
        float4 wh0 = *(const float4*)(tab + (size_t)i0 * HID + HID + lane * 4);
        float4 h1  = *(const float4*)(g_h + (size_t)jt1.x * HID + lane * 4);
        float4 wl1 = *(const float4*)(tab + (size_t)i1 * HID + lane * 4);
        float4 wh1 = *(const float4*)(tab + (size_t)i1 * HID + HID + lane * 4);
        nx = fmaf(h0.x, fmaf(fr0, wh0.x - wl0.x, wl0.x), nx);
        ny = fmaf(h0.y, fmaf(fr0, wh0.y - wl0.y, wl0.y), ny);
        nz = fmaf(h0.z, fmaf(fr0, wh0.z - wl0.z, wl0.z), nz);
        nw = fmaf(h0.w, fmaf(fr0, wh0.w - wl0.w, wl0.w), nw);
        nx = fmaf(h1.x, fmaf(fr1, wh1.x - wl1.x, wl1.x), nx);
        ny = fmaf(h1.y, fmaf(fr1, wh1.y - wl1.y, wl1.y), ny);
        nz = fmaf(h1.z, fmaf(fr1, wh1.z - wl1.z, wl1.z), nz);
        nw = fmaf(h1.w, fmaf(fr1, wh1.w - wl1.w, wl1.w), nw);
    }
    if (e < mid) {
        int2  jt = __ldg(&g_jt[e]);
        float tt = __int_as_float(jt.y);
        int   i0 = (int)tt;
        float fr = tt - (float)i0;
        float4 hj = *(const float4*)(g_h + (size_t)jt.x * HID + lane * 4);
        float4 wl = *(const float4*)(tab + (size_t)i0 * HID + lane * 4);
        float4 wh = *(const float4*)(tab + (size_t)i0 * HID + HID + lane * 4);
        nx = fmaf(hj.x, fmaf(fr, wh.x - wl.x, wl.x), nx);
        ny = fmaf(hj.y, fmaf(fr, wh.y - wl.y, wl.y), ny);
        nz = fmaf(hj.z, fmaf(fr, wh.z - wl.z, wl.z), nz);
        nw = fmaf(hj.w, fmaf(fr, wh.w - wl.w, wl.w), nw);
    }

    // ---- far loop: pure h sum, unroll 4 ----
    float fx = 0.f, fy = 0.f, fz = 0.f, fw = 0.f;
    e = mid;
    for (; e + 4 <= hi; e += 4) {
        int j0 = __ldg(&g_jt[e    ].x);
        int j1 = __ldg(&g_jt[e + 1].x);
        int j2 = __ldg(&g_jt[e + 2].x);
        int j3 = __ldg(&g_jt[e + 3].x);
        float4 h0 = *(const float4*)(g_h + (size_t)j0 * HID + lane * 4);
        float4 h1 = *(const float4*)(g_h + (size_t)j1 * HID + lane * 4);
        float4 h2 = *(const float4*)(g_h + (size_t)j2 * HID + lane * 4);
        float4 h3 = *(const float4*)(g_h + (size_t)j3 * HID + lane * 4);
        fx += (h0.x + h1.x) + (h2.x + h3.x);
        fy += (h0.y + h1.y) + (h2.y + h3.y);
        fz += (h0.z + h1.z) + (h2.z + h3.z);
        fw += (h0.w + h1.w) + (h2.w + h3.w);
    }
    for (; e < hi; e++) {
        int j = __ldg(&g_jt[e].x);
        float4 hj = *(const float4*)(g_h + (size_t)j * HID + lane * 4);
        fx += hj.x; fy += hj.y; fz += hj.z; fw += hj.w;
    }

    const float4 wlast = *(const float4*)(tab + (size_t)(TBL - 1) * HID + lane * 4);
    float s = g_invd[w];
    float4 o;
    o.x = fmaf(fx, wlast.x, nx) * s;
    o.y = fmaf(fy, wlast.y, ny) * s;
    o.z = fmaf(fz, wlast.z, nz) * s;
    o.w = fmaf(fw, wlast.w, nw) * s;
    *(float4*)(g_aggr + (size_t)w * HID + lane * 4) = o;
}

// ------ fused 2-layer MLP with packed f32x2 FMAs:
// ------ Y = act2( ssp(X@W1+b1) @ W2 + b2 )
template <int ACT2>
__global__ void k_mlp(const float* __restrict__ X,
                      const float* __restrict__ W1, const float* __restrict__ B1,
                      const float* __restrict__ W2, const float* __restrict__ B2,
                      float* __restrict__ Y, int nrows) {
    __shared__ float As[64 * HID];
    const int tid = threadIdx.x;
    const int tr = tid >> 4;            // 0..15 -> 4 rows each
    const int tc = tid & 15;            // 0..15 -> 8 cols each
    const int row0 = blockIdx.x * 64;

    for (int u = tid; u < 64 * (HID / 4); u += 256) {
        int r = u >> 5, q = u & 31;
        int gr = row0 + r;
        float4 v = make_float4(0.f, 0.f, 0.f, 0.f);
        if (gr < nrows) v = *(const float4*)(X + (size_t)gr * HID + q * 4);
        *(float4*)(As + r * HID + q * 4) = v;
    }
    __syncthreads();

    u64 acc[4][4];                       // [row][col-pair], each holds 2 fp32

    // ---------------- stage 1 ----------------
    #pragma unroll
    for (int a = 0; a < 4; a++)
        #pragma unroll
        for (int b = 0; b < 4; b++) acc[a][b] = 0ull;

    for (int k = 0; k < HID; k += 4) {
        float av[4][4];
        #pragma unroll
        for (int r = 0; r < 4; r++) {
            float4 t = *(const float4*)(As + (tr * 4 + r) * HID + k);
            av[r][0] = t.x; av[r][1] = t.y; av[r][2] = t.z; av[r][3] = t.w;
        }
        #pragma unroll
        for (int kk = 0; kk < 4; kk++) {
            const ulonglong2* wp =
                (const ulonglong2*)(W1 + (size_t)(k + kk) * HID + tc * 8);
            ulonglong2 w0 = __ldg(wp);
            ulonglong2 w1 = __ldg(wp + 1);
            u64 bp0 = w0.x, bp1 = w0.y, bp2 = w1.x, bp3 = w1.y;
            #pragma unroll
            for (int r = 0; r < 4; r++) {
                u64 ap = pack2(av[r][kk], av[r][kk]);
                ffma2(acc[r][0], ap, bp0);
                ffma2(acc[r][1], ap, bp1);
                ffma2(acc[r][2], ap, bp2);
                ffma2(acc[r][3], ap, bp3);
            }
        }
    }
    float4 c0 = __ldg((const float4*)(B1 + tc * 8));
    float4 c1 = __ldg((const float4*)(B1 + tc * 8 + 4));
    float bias1[8] = {c0.x, c0.y, c0.z, c0.w, c1.x, c1.y, c1.z, c1.w};
    __syncthreads();   // all stage-1 reads of As done
    #pragma unroll
    for (int rr = 0; rr < 4; rr++) {
        float v[8];
        #pragma unroll
        for (int p = 0; p < 4; p++) unpack2(acc[rr][p], v[2 * p], v[2 * p + 1]);
        float4 s0, s1;
        s0.x = sspf(v[0] + bias1[0]);
        s0.y = sspf(v[1] + bias1[1]);
        s0.z = sspf(v[2] + bias1[2]);
        s0.w = sspf(v[3] + bias1[3]);
        s1.x = sspf(v[4] + bias1[4]);
        s1.y = sspf(v[5] + bias1[5]);
        s1.z = sspf(v[6] + bias1[6]);
        s1.w = sspf(v[7] + bias1[7]);
        *(float4*)(As + (tr * 4 + rr) * HID + tc * 8)     = s0;
        *(float4*)(As + (tr * 4 + rr) * HID + tc * 8 + 4) = s1;
    }
    __syncthreads();

    // ---------------- stage 2 ----------------
    #pragma unroll
    for (int a = 0; a < 4; a++)
        #pragma unroll
        for (int b = 0; b < 4; b++) acc[a][b] = 0ull;

    for (int k = 0; k < HID; k += 4) {
        float av[4][4];
        #pragma unroll
        for (int r = 0; r < 4; r++) {
            float4 t = *(const float4*)(As + (tr * 4 + r) * HID + k);
            av[r][0] = t.x; av[r][1] = t.y; av[r][2] = t.z; av[r][3] = t.w;
        }
        #pragma unroll
        for (int kk = 0; kk < 4; kk++) {
            const ulonglong2* wp =
                (const ulonglong2*)(W2 + (size_t)(k + kk) * HID + tc * 8);
            ulonglong2 w0 = __ldg(wp);
            ulonglong2 w1 = __ldg(wp + 1);
            u64 bp0 = w0.x, bp1 = w0.y, bp2 = w1.x, bp3 = w1.y;
            #pragma unroll
            for (int r = 0; r < 4; r++) {
                u64 ap = pack2(av[r][kk], av[r][kk]);
                ffma2(acc[r][0], ap, bp0);
                ffma2(acc[r][1], ap, bp1);
                ffma2(acc[r][2], ap, bp2);
                ffma2(acc[r][3], ap, bp3);
            }
        }
    }
    float4 d0 = __ldg((const float4*)(B2 + tc * 8));
    float4 d1 = __ldg((const float4*)(B2 + tc * 8 + 4));
    float bias2[8] = {d0.x, d0.y, d0.z, d0.w, d1.x, d1.y, d1.z, d1.w};

    #pragma unroll
    for (int rr = 0; rr < 4; rr++) {
        int gr = row0 + tr * 4 + rr;
        if (gr >= nrows) continue;
        float v[8];
        #pragma unroll
        for (int p = 0; p < 4; p++) unpack2(acc[rr][p], v[2 * p], v[2 * p + 1]);
        #pragma unroll
        for (int c = 0; c < 8; c++) {
            float t = v[c] + bias2[c];
            v[c] = (ACT2 ? sspf(t) : t);
        }
        float4 o0 = make_float4(v[0], v[1], v[2], v[3]);
        float4 o1 = make_float4(v[4], v[5], v[6], v[7]);
        *(float4*)(Y + (size_t)gr * HID + tc * 8)     = o0;
        *(float4*)(Y + (size_t)gr * HID + tc * 8 + 4) = o1;
    }
}

// ---------------- output reduction ----------------
__global__ void k_zero_out(float* out) {
    int g = blockIdx.x * blockDim.x + threadIdx.x;
    if (g < NG) out[g] = 0.0f;
}

__global__ void k_energy(const int* __restrict__ batch,
                         const float* __restrict__ ow3, const float* __restrict__ ob3,
                         float* __restrict__ out) {
    __shared__ float sv[8];
    __shared__ int   sg[8];
    int tid  = threadIdx.x;
    int w    = (blockIdx.x * blockDim.x + tid) >> 5;           // node
    int wid  = tid >> 5;
    int lane = tid & 31;
    float4 e  = *(const float4*)(g_aggr + (size_t)w * HID + lane * 4);
    float4 ww = *(const float4*)(ow3 + lane * 4);
    float v = e.x * ww.x + e.y * ww.y + e.z * ww.z + e.w * ww.w;
    #pragma unroll
    for (int o = 16; o > 0; o >>= 1) v += __shfl_down_sync(0xffffffffu, v, o);
    if (lane == 0) {
        sv[wid] = v + ob3[0];
        sg[wid] = batch[w];
    }
    __syncthreads();
    if (tid == 0) {
        // batch is sorted -> consecutive nodes usually share a graph
        float acc = sv[0];
        int   b   = sg[0];
        #pragma unroll
        for (int k = 1; k < 8; k++) {
            if (sg[k] == b) acc += sv[k];
            else { atomicAdd(&out[b], acc); b = sg[k]; acc = sv[k]; }
        }
        atomicAdd(&out[b], acc);
    }
}

// ---------------- launch ----------------
extern "C" void kernel_launch(void* const* d_in, const int* in_sizes, int n_in,
                              void* d_out, int out_size) {
    const int*   z     = (const int*)  d_in[0];
    const float* pos   = (const float*)d_in[1];
    const int*   ei    = (const int*)  d_in[2];
    const int*   batch = (const int*)  d_in[3];
    const float* embed = (const float*)d_in[4];
    const float* fw1   = (const float*)d_in[5];
    const float* fb1   = (const float*)d_in[6];
    const float* fw2   = (const float*)d_in[7];
    const float* fb2   = (const float*)d_in[8];
    const float* uw1   = (const float*)d_in[9];
    const float* ub1   = (const float*)d_in[10];
    const float* uw2   = (const float*)d_in[11];
    const float* ub2   = (const float*)d_in[12];
    const float* ow1   = (const float*)d_in[13];
    const float* ob1   = (const float*)d_in[14];
    const float* ow2   = (const float*)d_in[15];
    const float* ob2   = (const float*)d_in[16];
    const float* ow3   = (const float*)d_in[17];
    const float* ob3   = (const float*)d_in[18];
    float* out = (float*)d_out;

    float *p_h = nullptr, *p_aggr = nullptr;
    cudaGetSymbolAddress((void**)&p_h,    g_h);
    cudaGetSymbolAddress((void**)&p_aggr, g_aggr);

    // preprocessing (once per launch, amortized over 6 layers)
    k_init   <<<(NN * 32) / 256, 256>>>(z, embed);
    k_deg    <<<NE / 256, 256>>>(ei);
    k_scan   <<<1, 1024>>>();
    k_scatter<<<NE / 256, 256>>>(ei, pos);
    k_sort   <<<(NN + 255) / 256, 256>>>();
    k_table  <<<(NL * TBL) / 8, 128>>>(fw1, fb1, fw2, fb2);

    const int mlp_blocks  = (NN + 63) / 64;
    const int warp_blocks = (NN * 32) / 256;

    for (int l = 0; l < NL; l++) {
        k_edge<<<warp_blocks, 256>>>(l);
        k_mlp<0><<<mlp_blocks, 256>>>(p_aggr,
                                      uw1 + (size_t)l * HID * HID, ub1 + (size_t)l * HID,
                                      uw2 + (size_t)l * HID * HID, ub2 + (size_t)l * HID,
                                      p_h, NN);
    }
    // output block: e2 = ssp(ssp(h@ow1+b1)@ow2+b2) stored into g_aggr
    k_mlp<1><<<mlp_blocks, 256>>>(p_h, ow1, ob1, ow2, ob2, p_aggr, NN);
    k_zero_out<<<2, 256>>>(out);
    k_energy<<<warp_blocks, 256>>>(batch, ow3, ob3, out);
}

// round 5
// speedup vs baseline: 1.7271x; 1.7271x over previous
#include <cuda_runtime.h>
#include <cuda_bf16.h>
#include <math.h>

#define NN    50000      // nodes
#define NNP   50048      // padded to 16*8*391
#define NE    800000     // edges
#define NG    512        // graphs
#define HID   128
#define RBF   32
#define NL    6
#define TBL   5120       // LUT grid points per layer
#define DMAX  5.0f       // beyond this, rbf == 0 to fp32 precision

typedef unsigned long long u64;
typedef unsigned int u32;

// ---------------- device scratch (static allocations only) ----------------
__device__ float g_h    [NNP * HID];       // node features (padded, tail zero/benign)
__device__ float g_aggr [NNP * HID];       // aggregated messages / e2 reuse
__device__ float g_table[NL * TBL * HID];  // W_l(d) lookup table
__device__ int   g_deg  [NN];
__device__ float g_invd [NN];
__device__ int   g_off  [NN + 1];
__device__ int   g_cur  [NN];
__device__ int2  g_jt   [NE];              // CSR: {neighbor j, tt bits}
__device__ int   g_se   [NE];              // CSR: original edge id (sort key)
// mma-fragment-layout bf16 hi/lo weight images:
// [m:14][s:8][t:16][lane:32][4 x u32: bh0,bh1,bl0,bl1]
__device__ u32   g_wfrag[14 * 8 * 16 * 32 * 4];

__device__ __forceinline__ float sspf(float x) {
    return fmaxf(x, 0.0f) + log1pf(expf(-fabsf(x))) - 0.5f;
}

// pack two floats as bf16x2 (x -> low 16, y -> high 16)
__device__ __forceinline__ u32 packbf(float x, float y) {
    __nv_bfloat16 bx = __float2bfloat16(x);
    __nv_bfloat16 by = __float2bfloat16(y);
    return ((u32)__bfloat16_as_ushort(by) << 16) | (u32)__bfloat16_as_ushort(bx);
}
// hi/lo split of a float2 into packed bf16x2 pair
__device__ __forceinline__ void splitbf2(float x, float y, u32& hi, u32& lo) {
    __nv_bfloat16 bx = __float2bfloat16(x);
    __nv_bfloat16 by = __float2bfloat16(y);
    float rx = x - __bfloat162float(bx);
    float ry = y - __bfloat162float(by);
    hi = ((u32)__bfloat16_as_ushort(by) << 16) | (u32)__bfloat16_as_ushort(bx);
    lo = packbf(rx, ry);
}

__device__ __forceinline__ void mma_bf(float c[4], const u32 a[4], u32 b0, u32 b1) {
    asm volatile(
        "mma.sync.aligned.m16n8k16.row.col.f32.bf16.bf16.f32 "
        "{%0,%1,%2,%3}, {%4,%5,%6,%7}, {%8,%9}, {%0,%1,%2,%3};"
        : "+f"(c[0]), "+f"(c[1]), "+f"(c[2]), "+f"(c[3])
        : "r"(a[0]), "r"(a[1]), "r"(a[2]), "r"(a[3]), "r"(b0), "r"(b1));
}

// ---------------- init: h = embed[z], zero deg, zero padded tail -----------
__global__ void k_init(const int* __restrict__ z, const float* __restrict__ embed) {
    int tid  = blockIdx.x * blockDim.x + threadIdx.x;   // NNP*32 threads exactly
    int n    = tid >> 5;
    int lane = tid & 31;
    if (n >= NN) {                                      // padded tail: keep zero
        float4 zf = make_float4(0.f, 0.f, 0.f, 0.f);
        *(float4*)(g_h    + (size_t)n * HID + lane * 4) = zf;
        *(float4*)(g_aggr + (size_t)n * HID + lane * 4) = zf;
        return;
    }
    if (lane == 0) g_deg[n] = 0;
    int zz = z[n];
    float4 v = *(const float4*)(embed + (size_t)zz * HID + lane * 4);
    *(float4*)(g_h + (size_t)n * HID + lane * 4) = v;
}

// ---------------- degree count ----------------
__global__ void k_deg(const int* __restrict__ ei) {
    int e = blockIdx.x * blockDim.x + threadIdx.x;      // NE threads exactly
    atomicAdd(&g_deg[ei[e]], 1);
}

// ---------------- single-block exclusive scan over degrees ----------------
__global__ void k_scan() {
    __shared__ int sums[1024];
    const int t = threadIdx.x;
    const int CH = 49;                                  // 1024*49 >= NN
    int base = t * CH;
    int s = 0;
    for (int u = 0; u < CH; u++) {
        int idx = base + u;
        if (idx < NN) s += g_deg[idx];
    }
    sums[t] = s;
    __syncthreads();
    for (int o = 1; o < 1024; o <<= 1) {
        int v = (t >= o) ? sums[t - o] : 0;
        __syncthreads();
        sums[t] += v;
        __syncthreads();
    }
    int run = (t == 0) ? 0 : sums[t - 1];
    for (int u = 0; u < CH; u++) {
        int idx = base + u;
        if (idx < NN) {
            int d = g_deg[idx];
            g_off[idx] = run;
            g_cur[idx] = run;
            g_invd[idx] = 1.0f / (float)max(d, 1);
            run += d;
        }
    }
    if (t == 1023) g_off[NN] = sums[1023];
}

// ---------------- compute d, scatter edges into CSR buckets ----------------
__global__ void k_scatter(const int* __restrict__ ei, const float* __restrict__ pos) {
    int e = blockIdx.x * blockDim.x + threadIdx.x;      // NE threads exactly
    int i = ei[e];
    int j = ei[NE + e];
    float dx = pos[3 * i + 0] - pos[3 * j + 0];
    float dy = pos[3 * i + 1] - pos[3 * j + 1];
    float dz = pos[3 * i + 2] - pos[3 * j + 2];
    float d  = sqrtf(dx * dx + dy * dy + dz * dz);
    const float inv_step = (float)(TBL - 1) / DMAX;
    float tt = fminf(d * inv_step, (float)(TBL - 1));
    int p = atomicAdd(&g_cur[i], 1);
    g_jt[p] = make_int2(j, __float_as_int(tt));
    g_se[p] = e;
}

// --------- deterministic order: insertion sort each bucket by edge id ------
__global__ void k_sort() {
    int n = blockIdx.x * blockDim.x + threadIdx.x;
    if (n >= NN) return;
    int lo = g_off[n], hi = g_off[n + 1];
    for (int a = lo + 1; a < hi; a++) {
        int  ke = g_se[a];
        int2 kv = g_jt[a];
        int b = a - 1;
        while (b >= lo && g_se[b] > ke) {
            g_se[b + 1] = g_se[b];
            g_jt[b + 1] = g_jt[b];
            b--;
        }
        g_se[b + 1] = ke;
        g_jt[b + 1] = kv;
    }
}

// ---------------- build W_l(d) table: 8 grid points per block --------------
__global__ void k_table(const float* __restrict__ fw1, const float* __restrict__ fb1,
                        const float* __restrict__ fw2, const float* __restrict__ fb2) {
    const int PG = 8;
    int gid = blockIdx.x * PG;          // over NL*TBL
    int l   = gid / TBL;
    int g0  = gid - l * TBL;
    int c   = threadIdx.x;              // 128 threads
    __shared__ float rbf [PG][RBF];
    __shared__ float sspt[PG][HID];
    const float step   = DMAX / (float)(TBL - 1);
    const float cspace = 4.0f / 31.0f;

    for (int u = c; u < PG * RBF; u += HID) {
        int p = u >> 5, k = u & 31;
        float d = (float)(g0 + p) * step;
        float x = d - (float)k * cspace;
        rbf[p][k] = expf(-32.0f * x * x);
    }
    __syncthreads();

    float acc[PG];
    float b1 = fb1[l * HID + c];
    #pragma unroll
    for (int p = 0; p < PG; p++) acc[p] = b1;
    for (int k = 0; k < RBF; k++) {
        float f = fw1[(size_t)(l * RBF + k) * HID + c];
        #pragma unroll
        for (int p = 0; p < PG; p++) acc[p] = fmaf(rbf[p][k], f, acc[p]);
    }
    #pragma unroll
    for (int p = 0; p < PG; p++) sspt[p][c] = sspf(acc[p]);
    __syncthreads();

    float b2 = fb2[l * HID + c];
    #pragma unroll
    for (int p = 0; p < PG; p++) acc[p] = b2;
    for (int m = 0; m < HID; m++) {
        float f = fw2[(size_t)(l * HID + m) * HID + c];
        #pragma unroll
        for (int p = 0; p < PG; p++) acc[p] = fmaf(sspt[p][m], f, acc[p]);
    }
    #pragma unroll
    for (int p = 0; p < PG; p++)
        g_table[((size_t)l * TBL + g0 + p) * HID + c] = acc[p];
}

// -------- weight images in mma B-fragment layout (bf16 hi/lo) --------------
// matrix m: m=2l -> uw1[l], m=2l+1 -> uw2[l] (l<6); m=12 -> ow1; m=13 -> ow2
__global__ void k_prepw(const float* __restrict__ uw1, const float* __restrict__ uw2,
                        const float* __restrict__ ow1, const float* __restrict__ ow2) {
    int idx  = blockIdx.x * blockDim.x + threadIdx.x;   // 14*8*16*32 threads exactly
    int lane = idx & 31;
    int t    = (idx >> 5) & 15;
    int s    = (idx >> 9) & 7;
    int m    = idx >> 12;
    const float* W;
    if (m < 12)       W = (m & 1) ? (uw2 + (size_t)(m >> 1) * 16384)
                                  : (uw1 + (size_t)(m >> 1) * 16384);
    else if (m == 12) W = ow1;
    else              W = ow2;
    int g    = lane >> 2;
    int tid2 = (lane & 3) * 2;
    int n    = t * 8 + g;
    int k0   = s * 16 + tid2;
    float v00 = W[(size_t)k0 * HID + n];
    float v01 = W[(size_t)(k0 + 1) * HID + n];
    float v10 = W[(size_t)(k0 + 8) * HID + n];
    float v11 = W[(size_t)(k0 + 9) * HID + n];
    uint4 o;
    u32 lo0, lo1;
    splitbf2(v00, v01, o.x, lo0);
    splitbf2(v10, v11, o.y, lo1);
    o.z = lo0;
    o.w = lo1;
    *(uint4*)(g_wfrag + (size_t)idx * 4) = o;
}

// --------- per-layer edge aggregation: one warp per node, far fast path ----
__global__ void k_edge(int l) {
    int w    = (blockIdx.x * blockDim.x + threadIdx.x) >> 5;  // == node, exact
    int lane = threadIdx.x & 31;
    int lo = g_off[w], hi = g_off[w + 1];
    const float* tab = g_table + (size_t)l * TBL * HID;
    const float4 wlast = *(const float4*)(tab + (size_t)(TBL - 1) * HID + lane * 4);
    const float TTMAX = (float)(TBL - 1);
    float nx = 0.f, ny = 0.f, nz = 0.f, nw = 0.f;   // near accum (lerped)
    float fx = 0.f, fy = 0.f, fz = 0.f, fw = 0.f;   // far accum (h sum)
    for (int e = lo; e < hi; e++) {
        int2  jt = __ldg(&g_jt[e]);
        int   j  = jt.x;
        float tt = __int_as_float(jt.y);
        float4 hj = *(const float4*)(g_h + (size_t)j * HID + lane * 4);
        if (tt >= TTMAX) {                           // lane-uniform branch
            fx += hj.x; fy += hj.y; fz += hj.z; fw += hj.w;
        } else {
            int   idx = (int)tt;
            float fr  = tt - (float)idx;
            float4 wl = *(const float4*)(tab + (size_t)idx * HID + lane * 4);
            float4 wh = *(const float4*)(tab + (size_t)idx * HID + HID + lane * 4);
            nx = fmaf(hj.x, fmaf(fr, wh.x - wl.x, wl.x), nx);
            ny = fmaf(hj.y, fmaf(fr, wh.y - wl.y, wl.y), ny);
            nz = fmaf(hj.z, fmaf(fr, wh.z - wl.z, wl.z), nz);
            nw = fmaf(hj.w, fmaf(fr, wh.w - wl.w, wl.w), nw);
        }
    }
    float s = g_invd[w];
    float4 o;
    o.x = fmaf(fx, wlast.x, nx) * s;
    o.y = fmaf(fy, wlast.y, ny) * s;
    o.z = fmaf(fz, wlast.z, nz) * s;
    o.w = fmaf(fw, wlast.w, nw) * s;
    *(float4*)(g_aggr + (size_t)w * HID + lane * 4) = o;
}

// ---------- tensor-core fused 2-layer MLP (mma.sync bf16, 3-term split) ----
// Y = act2( ssp(X@W1+b1) @ W2 + b2 ). Each warp: 16 rows x 128 cols, K=128.
// No shared memory, no block syncs. Stage-1 D frags ARE stage-2 A frags.
template <int ACT2>
__global__ void __launch_bounds__(256, 1)
k_mlp_mma(const float* __restrict__ X,
          const u32* __restrict__ WF1, const float* __restrict__ B1,
          const u32* __restrict__ WF2, const float* __restrict__ B2,
          float* __restrict__ Y) {
    const int lane  = threadIdx.x & 31;
    const int warp  = (blockIdx.x * blockDim.x + threadIdx.x) >> 5;  // 0..3127
    const int rbase = warp * 16;                                     // < NNP
    const int g     = lane >> 2;
    const int tid2  = (lane & 3) * 2;
    const float* xr0 = X + (size_t)(rbase + g) * HID;
    const float* xr1 = X + (size_t)(rbase + g + 8) * HID;

    float acc[16][4];
    #pragma unroll
    for (int t = 0; t < 16; t++)
        #pragma unroll
        for (int q = 0; q < 4; q++) acc[t][q] = 0.f;

    // ---------------- stage 1 ----------------
    const uint4* wf1 = (const uint4*)WF1;
    #pragma unroll
    for (int s = 0; s < 8; s++) {
        int k0 = s * 16 + tid2;
        float2 x00 = *(const float2*)(xr0 + k0);
        float2 x10 = *(const float2*)(xr1 + k0);
        float2 x01 = *(const float2*)(xr0 + k0 + 8);
        float2 x11 = *(const float2*)(xr1 + k0 + 8);
        u32 ah[4], al[4];
        splitbf2(x00.x, x00.y, ah[0], al[0]);
        splitbf2(x10.x, x10.y, ah[1], al[1]);
        splitbf2(x01.x, x01.y, ah[2], al[2]);
        splitbf2(x11.x, x11.y, ah[3], al[3]);
        const uint4* bp = wf1 + (size_t)s * 512 + lane;
        #pragma unroll
        for (int t = 0; t < 16; t++) {
            uint4 b = __ldg(bp + t * 32);           // bh0,bh1,bl0,bl1
            mma_bf(acc[t], ah, b.x, b.y);
            mma_bf(acc[t], ah, b.z, b.w);
            mma_bf(acc[t], al, b.x, b.y);
        }
    }

    // ---- epilogue 1: bias + ssp, D frags -> stage-2 A frags (in register) --
    u32 a2h[8][4], a2l[8][4];
    #pragma unroll
    for (int s = 0; s < 8; s++) {
        #pragma unroll
        for (int hf = 0; hf < 2; hf++) {
            int t = 2 * s + hf;
            float2 bias = *(const float2*)(B1 + t * 8 + tid2);
            float d0 = sspf(acc[t][0] + bias.x);
            float d1 = sspf(acc[t][1] + bias.y);
            float d2 = sspf(acc[t][2] + bias.x);
            float d3 = sspf(acc[t][3] + bias.y);
            splitbf2(d0, d1, a2h[s][2 * hf + 0], a2l[s][2 * hf + 0]);
            splitbf2(d2, d3, a2h[s][2 * hf + 1], a2l[s][2 * hf + 1]);
        }
    }
    // a-frag order: a0 = tile2s(c0,c1), a1 = tile2s(c2,c3),
    //               a2 = tile2s+1(c0,c1), a3 = tile2s+1(c2,c3)
    // built above as [2*hf+0]=(c0,c1), [2*hf+1]=(c2,c3) -> indices {0,1,2,3} ✓

    #pragma unroll
    for (int t = 0; t < 16; t++)
        #pragma unroll
        for (int q = 0; q < 4; q++) acc[t][q] = 0.f;

    // ---------------- stage 2 ----------------
    const uint4* wf2 = (const uint4*)WF2;
    #pragma unroll
    for (int s = 0; s < 8; s++) {
        const uint4* bp = wf2 + (size_t)s * 512 + lane;
        #pragma unroll
        for (int t = 0; t < 16; t++) {
            uint4 b = __ldg(bp + t * 32);
            mma_bf(acc[t], a2h[s], b.x, b.y);
            mma_bf(acc[t], a2h[s], b.z, b.w);
            mma_bf(acc[t], a2l[s], b.x, b.y);
        }
    }

    // ---- epilogue 2: bias (+ act2), store ----
    float* yr0 = Y + (size_t)(rbase + g) * HID;
    float* yr1 = Y + (size_t)(rbase + g + 8) * HID;
    #pragma unroll
    for (int t = 0; t < 16; t++) {
        float2 bias = *(const float2*)(B2 + t * 8 + tid2);
        float o0 = acc[t][0] + bias.x;
        float o1 = acc[t][1] + bias.y;
        float o2 = acc[t][2] + bias.x;
        float o3 = acc[t][3] + bias.y;
        if (ACT2) { o0 = sspf(o0); o1 = sspf(o1); o2 = sspf(o2); o3 = sspf(o3); }
        *(float2*)(yr0 + t * 8 + tid2) = make_float2(o0, o1);
        *(float2*)(yr1 + t * 8 + tid2) = make_float2(o2, o3);
    }
}

// ---------------- output reduction ----------------
__global__ void k_zero_out(float* out) {
    int g = blockIdx.x * blockDim.x + threadIdx.x;
    if (g < NG) out[g] = 0.0f;
}

__global__ void k_energy(const int* __restrict__ batch,
                         const float* __restrict__ ow3, const float* __restrict__ ob3,
                         float* __restrict__ out) {
    int w    = (blockIdx.x * blockDim.x + threadIdx.x) >> 5;   // node
    int lane = threadIdx.x & 31;
    float4 e  = *(const float4*)(g_aggr + (size_t)w * HID + lane * 4);
    float4 ww = *(const float4*)(ow3 + lane * 4);
    float v = e.x * ww.x + e.y * ww.y + e.z * ww.z + e.w * ww.w;
    #pragma unroll
    for (int o = 16; o > 0; o >>= 1) v += __shfl_down_sync(0xffffffffu, v, o);
    if (lane == 0) atomicAdd(&out[batch[w]], v + ob3[0]);
}

// ---------------- launch ----------------
extern "C" void kernel_launch(void* const* d_in, const int* in_sizes, int n_in,
                              void* d_out, int out_size) {
    const int*   z     = (const int*)  d_in[0];
    const float* pos   = (const float*)d_in[1];
    const int*   ei    = (const int*)  d_in[2];
    const int*   batch = (const int*)  d_in[3];
    const float* embed = (const float*)d_in[4];
    const float* fw1   = (const float*)d_in[5];
    const float* fb1   = (const float*)d_in[6];
    const float* fw2   = (const float*)d_in[7];
    const float* fb2   = (const float*)d_in[8];
    const float* uw1   = (const float*)d_in[9];
    const float* ub1   = (const float*)d_in[10];
    const float* uw2   = (const float*)d_in[11];
    const float* ub2   = (const float*)d_in[12];
    const float* ow1   = (const float*)d_in[13];
    const float* ob1   = (const float*)d_in[14];
    const float* ow2   = (const float*)d_in[15];
    const float* ob2   = (const float*)d_in[16];
    const float* ow3   = (const float*)d_in[17];
    const float* ob3   = (const float*)d_in[18];
    float* out = (float*)d_out;

    float *p_h = nullptr, *p_aggr = nullptr;
    u32*   p_wf = nullptr;
    cudaGetSymbolAddress((void**)&p_h,    g_h);
    cudaGetSymbolAddress((void**)&p_aggr, g_aggr);
    cudaGetSymbolAddress((void**)&p_wf,   g_wfrag);

    // preprocessing (once per launch, amortized over 6 layers)
    k_init   <<<(NNP * 32) / 256, 256>>>(z, embed);
    k_deg    <<<NE / 256, 256>>>(ei);
    k_scan   <<<1, 1024>>>();
    k_scatter<<<NE / 256, 256>>>(ei, pos);
    k_sort   <<<(NN + 255) / 256, 256>>>();
    k_table  <<<(NL * TBL) / 8, 128>>>(fw1, fb1, fw2, fb2);
    k_prepw  <<<(14 * 8 * 16 * 32) / 256, 256>>>(uw1, uw2, ow1, ow2);

    const int mma_blocks  = NNP / 128;            // 391 blocks x 8 warps x 16 rows
    const int warp_blocks = (NN * 32) / 256;

    for (int l = 0; l < NL; l++) {
        k_edge<<<warp_blocks, 256>>>(l);
        k_mlp_mma<0><<<mma_blocks, 256>>>(
            p_aggr,
            p_wf + (size_t)(2 * l)     * 16384, ub1 + (size_t)l * HID,
            p_wf + (size_t)(2 * l + 1) * 16384, ub2 + (size_t)l * HID,
            p_h);
    }
    // output block: e2 = ssp(ssp(h@ow1+b1)@ow2+b2) stored into g_aggr
    k_mlp_mma<1><<<mma_blocks, 256>>>(
        p_h,
        p_wf + (size_t)12 * 16384, ob1,
        p_wf + (size_t)13 * 16384, ob2,
        p_aggr);
    k_zero_out<<<2, 256>>>(out);
    k_energy<<<warp_blocks, 256>>>(batch, ow3, ob3, out);
}